// round 1
// baseline (speedup 1.0000x reference)
#include <cuda_runtime.h>
#include <cstdint>

// ---------------------------------------------------------------------------
// ActorNetSpikingwithRSTDP: 4-layer LIF SNN scan, T=50 steps.
//   B=4096, S=256, H=256, A=2.
// Strategy: persistent-per-block batch partitioning. Each block owns MB=14
// batch rows and runs the full 50-step scan with all LIF state resident
// (u in smem, masked/decayed v in registers). Thread j owns output neuron j.
// Exact fp32 numerics: k-ascending single-accumulator FMA per output,
// elementwise ops in the reference's evaluation order.
// ---------------------------------------------------------------------------

namespace {

constexpr int Bb = 4096;
constexpr int Ss = 256;
constexpr int Tt = 50;
constexpr int Hh = 256;
constexpr int Aa = 2;

constexpr int MB = 14;                       // batch rows per block
constexpr int PS = 260;                      // padded pre/spike row stride (floats)
constexpr int NBLK = (Bb + MB - 1) / MB;     // 293 blocks

constexpr float CDECAY = 0.5f;
constexpr float VDECAY = 0.75f;
constexpr float VTH    = 0.5f;

// smem layout (floats)
constexpr int OFF_XE = 0;                    // x tile        [MB][PS]
constexpr int OFF_SA = OFF_XE + MB * PS;     // spike buf A   [MB][PS]
constexpr int OFF_SB = OFF_SA + MB * PS;     // spike buf B   [MB][PS]
constexpr int OFF_US = OFF_SB + MB * PS;     // u state       [3][MB][Hh]
constexpr int OFF_W4 = OFF_US + 3 * MB * Hh; // w4 staging    [Hh*Aa]
constexpr int SMEM_FLOATS = OFF_W4 + Hh * Aa;
constexpr int SMEM_BYTES  = SMEM_FLOATS * 4; // 88,736 B

}  // namespace

// One LIF layer for this block: cur = u*0.5 + pre@W + b ; volt = vm + cur ;
// spk = volt > 0.5 ; carry u=cur, vm=(volt*0.75)*(1-spk).
__device__ __forceinline__ void lif_layer(
    const float* __restrict__ W,     // [Hh][Hh], row k, col j
    float bias,
    const float* __restrict__ pre,   // smem [MB][PS]
    float* __restrict__ spk,         // smem [MB][PS]
    float* __restrict__ u_s,         // smem [MB][Hh] for this layer
    float (&vm)[MB],                 // registers: (v*0.75)*(1-s) carried state
    int j)
{
    float acc[MB];
#pragma unroll
    for (int b = 0; b < MB; ++b) acc[b] = 0.0f;

    // GEMM: acc[b] = sum_k pre[b][k] * W[k][j], k strictly ascending.
#pragma unroll 2
    for (int k4 = 0; k4 < Hh / 4; ++k4) {
        const int k = k4 * 4;
        const float w0 = __ldg(&W[(k + 0) * Hh + j]);
        const float w1 = __ldg(&W[(k + 1) * Hh + j]);
        const float w2 = __ldg(&W[(k + 2) * Hh + j]);
        const float w3 = __ldg(&W[(k + 3) * Hh + j]);
#pragma unroll
        for (int b = 0; b < MB; ++b) {
            const float4 p = *reinterpret_cast<const float4*>(&pre[b * PS + k]);
            acc[b] = __fmaf_rn(p.x, w0, acc[b]);
            acc[b] = __fmaf_rn(p.y, w1, acc[b]);
            acc[b] = __fmaf_rn(p.z, w2, acc[b]);
            acc[b] = __fmaf_rn(p.w, w3, acc[b]);
        }
    }

#pragma unroll
    for (int b = 0; b < MB; ++b) {
        const float u    = u_s[b * Hh + j];
        const float cur  = __fadd_rn(__fadd_rn(__fmul_rn(u, CDECAY), acc[b]), bias);
        const float volt = __fadd_rn(vm[b], cur);
        const float s    = (volt > VTH) ? 1.0f : 0.0f;
        u_s[b * Hh + j]  = cur;
        vm[b] = __fmul_rn(__fmul_rn(volt, VDECAY), __fsub_rn(1.0f, s));
        spk[b * PS + j]  = s;
    }
}

__global__ void __launch_bounds__(256, 2) snn_persist(
    const float* __restrict__ x,
    const float* __restrict__ w1, const float* __restrict__ b1,
    const float* __restrict__ w2, const float* __restrict__ b2,
    const float* __restrict__ w3, const float* __restrict__ b3,
    const float* __restrict__ w4, const float* __restrict__ b4,
    float* __restrict__ out)
{
    extern __shared__ float sm[];
    float* xe  = sm + OFF_XE;
    float* sa  = sm + OFF_SA;
    float* sb  = sm + OFF_SB;
    float* us  = sm + OFF_US;
    float* w4s = sm + OFF_W4;

    const int j  = threadIdx.x;       // output neuron index, 0..255
    const int b0 = blockIdx.x * MB;   // first batch row of this block

    // Zero-init u state; stage w4 into smem.
#pragma unroll
    for (int l = 0; l < 3; ++l)
#pragma unroll
        for (int b = 0; b < MB; ++b)
            us[(l * MB + b) * Hh + j] = 0.0f;
    w4s[j]       = w4[j];
    w4s[j + 256] = w4[j + 256];

    float vm1[MB], vm2[MB], vm3[MB];
#pragma unroll
    for (int b = 0; b < MB; ++b) { vm1[b] = 0.0f; vm2[b] = 0.0f; vm3[b] = 0.0f; }

    const float bias1 = b1[j];
    const float bias2 = b2[j];
    const float bias3 = b3[j];

    // Layer 4 handled by threads 0..2*MB-1 (thread = (row, action)).
    const int l4b = j >> 1;
    const int l4a = j & 1;
    float u4 = 0.0f, v4m = 0.0f, s4sum = 0.0f, bias4 = 0.0f;
    if (j < 2 * MB) bias4 = b4[l4a];

    float xhold[MB];  // x values for the next (odd) timestep

    for (int t = 0; t < Tt; ++t) {
        __syncthreads();  // prev-iter readers of xe/sa are done

        // Stage x[:, :, t] for this block's rows. x is [B][S][T]; t and t+1
        // are adjacent, so load an aligned float2 per (b,s) on even t.
        if ((t & 1) == 0) {
#pragma unroll
            for (int i = 0; i < MB; ++i) {
                int bg = b0 + i;
                if (bg >= Bb) bg = Bb - 1;  // clamp phantom rows (safe, masked at store)
                const float2 p = *reinterpret_cast<const float2*>(
                    &x[((size_t)bg * Ss + j) * (size_t)Tt + t]);
                xe[i * PS + j] = p.x;
                xhold[i]       = p.y;
            }
        } else {
#pragma unroll
            for (int i = 0; i < MB; ++i) xe[i * PS + j] = xhold[i];
        }
        __syncthreads();

        lif_layer(w1, bias1, xe, sa, us + 0 * MB * Hh, vm1, j);
        __syncthreads();
        lif_layer(w2, bias2, sa, sb, us + 1 * MB * Hh, vm2, j);
        __syncthreads();
        lif_layer(w3, bias3, sb, sa, us + 2 * MB * Hh, vm3, j);
        __syncthreads();

        // Layer 4: [MB,256]@[256,2] + LIF + spike accumulation.
        if (j < 2 * MB) {
            float acc = 0.0f;
            const float4* row4 = reinterpret_cast<const float4*>(sa + l4b * PS);
#pragma unroll 4
            for (int k4 = 0; k4 < Hh / 4; ++k4) {
                const float4 p = row4[k4];
                acc = __fmaf_rn(p.x, w4s[(4 * k4 + 0) * Aa + l4a], acc);
                acc = __fmaf_rn(p.y, w4s[(4 * k4 + 1) * Aa + l4a], acc);
                acc = __fmaf_rn(p.z, w4s[(4 * k4 + 2) * Aa + l4a], acc);
                acc = __fmaf_rn(p.w, w4s[(4 * k4 + 3) * Aa + l4a], acc);
            }
            const float cur  = __fadd_rn(__fadd_rn(__fmul_rn(u4, CDECAY), acc), bias4);
            const float volt = __fadd_rn(v4m, cur);
            const float s    = (volt > VTH) ? 1.0f : 0.0f;
            u4  = cur;
            v4m = __fmul_rn(__fmul_rn(volt, VDECAY), __fsub_rn(1.0f, s));
            s4sum = __fadd_rn(s4sum, s);
        }
    }

    if (j < 2 * MB) {
        const int bg = b0 + l4b;
        if (bg < Bb) {
            // out = (sum/T)/T, mirroring the reference's two divisions
            out[bg * Aa + l4a] =
                __fdiv_rn(__fdiv_rn(s4sum, (float)Tt), (float)Tt);
        }
    }
}

extern "C" void kernel_launch(void* const* d_in, const int* in_sizes, int n_in,
                              void* d_out, int out_size)
{
    const float* x  = (const float*)d_in[0];
    const float* w1 = (const float*)d_in[1];
    const float* b1 = (const float*)d_in[2];
    const float* w2 = (const float*)d_in[3];
    const float* b2 = (const float*)d_in[4];
    const float* w3 = (const float*)d_in[5];
    const float* b3 = (const float*)d_in[6];
    const float* w4 = (const float*)d_in[7];
    const float* b4 = (const float*)d_in[8];
    float* out = (float*)d_out;
    (void)in_sizes; (void)n_in; (void)out_size;

    cudaFuncSetAttribute(snn_persist,
                         cudaFuncAttributeMaxDynamicSharedMemorySize,
                         SMEM_BYTES);

    snn_persist<<<NBLK, 256, SMEM_BYTES>>>(x, w1, b1, w2, b2, w3, b3, w4, b4, out);
}